// round 11
// baseline (speedup 1.0000x reference)
#include <cuda_runtime.h>
#include <cuda_fp16.h>
#include <mma.h>
#include <math.h>

using namespace nvcuda;

#define Bsz 128
#define Nn  512
#define Ff  64
#define Dd  64
#define Kk  20
#define BN  (Bsz*Nn)          // 65536
#define NELEM (BN*Dd)         // 4194304
#define AGRID 512             // 4 blocks per batch
#define H1_BLOCKS   1024

// ---------------- device scratch (no allocations allowed) ----------------
__device__ __half2 d_gh2[NELEM/2];        // g in fp16, [row][64]
__device__ __half2 d_aggh[NELEM/2];       // agg in fp16, [row][64]
__device__ float d_enorm[Nn*Dd];
__device__ float d_si[BN];
__device__ float d_sj[BN];
__device__ float d_eai[Nn];
__device__ float d_eaj[Nn];
__device__ int   d_topk[Nn*Kk];
__device__ float d_ps1[64*AGRID];         // channel-major BN1 partials
__device__ float d_pq1[64*AGRID];
__device__ float d_ps2[64*H1_BLOCKS];     // channel-major BN2 partials
__device__ float d_pq2[64*H1_BLOCKS];
__device__ float d_scale1[64], d_shift1[64], d_scale2[64], d_shift2[64];

__device__ __forceinline__ float warpSum(float v){
  #pragma unroll
  for(int o=16;o;o>>=1) v += __shfl_xor_sync(0xffffffffu, v, o);
  return v;
}

// ---- K1: normalize embed rows, per-node embed-attention scalars ----
__global__ void k_embed(const float* __restrict__ embed,
                        const float* __restrict__ aemi,
                        const float* __restrict__ aemj){
  int gw   = (blockIdx.x*blockDim.x + threadIdx.x) >> 5;
  int lane = threadIdx.x & 31;
  if(gw >= Nn) return;
  float v0 = embed[gw*64+lane];
  float v1 = embed[gw*64+32+lane];
  float ss = warpSum(v0*v0 + v1*v1);
  float inv = 1.0f/(sqrtf(ss)+1e-12f);
  d_enorm[gw*64+lane]    = v0*inv;
  d_enorm[gw*64+32+lane] = v1*inv;
  float si = warpSum(v0*aemi[lane] + v1*aemi[lane+32]);
  float sj = warpSum(v0*aemj[lane] + v1*aemj[lane+32]);
  if(lane==0){ d_eai[gw]=si; d_eaj[gw]=sj; }
}

// ---- K2: warp-per-node topk, sims register-resident ----
__global__ void k_topk(){
  __shared__ float tile[64*68];
  __shared__ float srows[8*68];
  int t = threadIdx.x, w = t>>5, lane = t&31;
  int node = blockIdx.x*8 + w;

  if(t < 128){
    int r = t >> 4, c4 = t & 15;
    float4 v = reinterpret_cast<const float4*>(d_enorm)[(blockIdx.x*8 + r)*16 + c4];
    *reinterpret_cast<float4*>(&srows[r*68 + c4*4]) = v;
  }

  float sims[16];
  #pragma unroll
  for(int chunk=0; chunk<8; chunk++){
    __syncthreads();
    #pragma unroll
    for(int q=0; q<4; q++){
      int idx = t + q*256;
      int r = idx >> 4, c4 = idx & 15;
      float4 v = reinterpret_cast<const float4*>(d_enorm)[(chunk*64 + r)*16 + c4];
      *reinterpret_cast<float4*>(&tile[r*68 + c4*4]) = v;
    }
    __syncthreads();
    const float* sr = &srows[w*68];
    float a0 = 0.f, a1 = 0.f;
    #pragma unroll
    for(int kk=0; kk<64; kk+=4){
      float4 s4 = *reinterpret_cast<const float4*>(&sr[kk]);
      float4 e0 = *reinterpret_cast<const float4*>(&tile[lane*68+kk]);
      float4 e1 = *reinterpret_cast<const float4*>(&tile[(lane+32)*68+kk]);
      a0 += s4.x*e0.x + s4.y*e0.y + s4.z*e0.z + s4.w*e0.w;
      a1 += s4.x*e1.x + s4.y*e1.y + s4.z*e1.z + s4.w*e1.w;
    }
    sims[chunk*2]   = a0;
    sims[chunk*2+1] = a1;
  }

  for(int sel=0; sel<Kk; sel++){
    float bv = -INFINITY; int bj = 0x3fffffff;
    #pragma unroll
    for(int s=0; s<16; s++){
      float v = sims[s];
      int j = (s>>1)*64 + (s&1)*32 + lane;
      if(v > bv || (v == bv && j < bj)){ bv = v; bj = j; }
    }
    #pragma unroll
    for(int o=16; o; o>>=1){
      float ov = __shfl_xor_sync(0xffffffffu, bv, o);
      int   oj = __shfl_xor_sync(0xffffffffu, bj, o);
      if(ov > bv || (ov == bv && oj < bj)){ bv = ov; bj = oj; }
    }
    if(lane==0) d_topk[node*Kk+sel] = bj;
    int wslot = ((bj>>6)<<1) | ((bj>>5)&1);
    bool own = ((bj & 31) == lane);
    #pragma unroll
    for(int s=0; s<16; s++) if(own && s==wslot) sims[s] = -INFINITY;
  }
}

// ---- K3: g = x @ W_lin via WMMA (half inputs, fp32 accum), + s_i/s_j ----
#define GS_XH 0
#define GS_WH 18432
#define GS_CS 27648
#define GEMM_SMEM (27648 + 128*68*4)   // 62464

__global__ void __launch_bounds__(256,3) k_gemm(const float* __restrict__ x,
                       const float* __restrict__ W,
                       const float* __restrict__ ati, const float* __restrict__ atj){
  extern __shared__ char gsm[];
  __half* Xh = reinterpret_cast<__half*>(gsm + GS_XH);
  __half* Wh = reinterpret_cast<__half*>(gsm + GS_WH);
  float*  Cs = reinterpret_cast<float*>(gsm + GS_CS);
  __shared__ float s_si[128][2], s_sj[128][2];

  int t = threadIdx.x;

  const float2* W2 = reinterpret_cast<const float2*>(W);
  #pragma unroll
  for(int q=0; q<8; q++){
    int idx = q*256 + t;
    float2 wv = W2[idx];
    int r = idx >> 5, c2 = idx & 31;
    reinterpret_cast<__half2*>(Wh + r*72)[c2] = __floats2half2_rn(wv.x, wv.y);
  }
  const float2* X2 = reinterpret_cast<const float2*>(x + (size_t)blockIdx.x*128*64);
  #pragma unroll
  for(int q=0; q<16; q++){
    int idx = q*256 + t;
    float2 xv = X2[idx];
    int r = idx >> 5, c2 = idx & 31;
    reinterpret_cast<__half2*>(Xh + r*72)[c2] = __floats2half2_rn(xv.x, xv.y);
  }
  __syncthreads();

  int w = t >> 5;
  wmma::fragment<wmma::accumulator,16,16,16,float> acc[4];
  #pragma unroll
  for(int n=0; n<4; n++) wmma::fill_fragment(acc[n], 0.0f);
  #pragma unroll
  for(int k=0; k<4; k++){
    wmma::fragment<wmma::matrix_a,16,16,16,__half,wmma::row_major> fa;
    wmma::load_matrix_sync(fa, Xh + (w*16)*72 + k*16, 72);
    #pragma unroll
    for(int n=0; n<4; n++){
      wmma::fragment<wmma::matrix_b,16,16,16,__half,wmma::row_major> fb;
      wmma::load_matrix_sync(fb, Wh + (k*16)*72 + n*16, 72);
      wmma::mma_sync(acc[n], fa, fb, acc[n]);
    }
  }
  #pragma unroll
  for(int n=0; n<4; n++)
    wmma::store_matrix_sync(Cs + (w*16)*68 + n*16, acc[n], 68, wmma::mem_row_major);
  __syncthreads();

  int row = t >> 1, hf = t & 1;
  const float* crow = Cs + row*68 + hf*32;
  float si = 0.f, sj = 0.f;
  union { __half2 h2[16]; uint4 u4[4]; } cv;
  #pragma unroll
  for(int q=0; q<8; q++){
    float4 c4 = *reinterpret_cast<const float4*>(crow + q*4);
    float4 av = *reinterpret_cast<const float4*>(ati + hf*32 + q*4);
    float4 aw = *reinterpret_cast<const float4*>(atj + hf*32 + q*4);
    si += c4.x*av.x + c4.y*av.y + c4.z*av.z + c4.w*av.w;
    sj += c4.x*aw.x + c4.y*aw.y + c4.z*aw.z + c4.w*aw.w;
    cv.h2[q*2]   = __floats2half2_rn(c4.x, c4.y);
    cv.h2[q*2+1] = __floats2half2_rn(c4.z, c4.w);
  }
  uint4* ghp = reinterpret_cast<uint4*>(d_gh2);
  int grow = blockIdx.x*128 + row;
  #pragma unroll
  for(int q=0; q<4; q++) ghp[(size_t)grow*8 + hf*4 + q] = cv.u4[q];
  s_si[row][hf] = si; s_sj[row][hf] = sj;
  __syncthreads();
  if(t < 128){
    int gr = blockIdx.x*128 + t;
    int node = gr & (Nn-1);
    d_si[gr] = s_si[t][0] + s_si[t][1] + d_eai[node];
    d_sj[gr] = s_sj[t][0] + s_sj[t][1] + d_eaj[node];
  }
}

// ---- K4: 4 blocks/batch, 512 threads; fp16 g slice in smem; fp16 agg out ----
#define ATTN_SMEM_FLOATS (16384 + 512 + 128)   // gh(64KB) + sj + si
#define ATTN_SMEM_BYTES  (ATTN_SMEM_FLOATS*4)

__global__ void __launch_bounds__(512,3) k_attn(const float* __restrict__ gnn_bias){
  extern __shared__ float sm[];
  __half2* gh_sm = reinterpret_cast<__half2*>(sm);   // [src*32 + lane]
  float* sj_sm = sm + 16384;   // 512
  float* si_sm = sm + 16896;   // 128 (this block's rows)

  int t = threadIdx.x, lane = t & 31, w = t >> 5;
  int b  = blockIdx.x >> 2;
  int row0 = (blockIdx.x & 3) * 128;

  const uint4* s4 = reinterpret_cast<const uint4*>(d_gh2 + (size_t)b*16384);
  uint4* dst4 = reinterpret_cast<uint4*>(sm);
  #pragma unroll
  for(int q=0; q<8; q++) dst4[q*512+t] = s4[q*512+t];
  sj_sm[t] = d_sj[b*512+t];
  if(t < 128) si_sm[t] = d_si[b*512 + row0 + t];
  __syncthreads();

  float2 bi2 = reinterpret_cast<const float2*>(gnn_bias)[lane];
  float2 ps = make_float2(0.f,0.f), pq = make_float2(0.f,0.f);

  for(int it=0; it<8; it++){
    int il = w*8 + it;            // local row 0..127
    int i  = row0 + il;           // node in batch
    unsigned packed;
    {
      int src = (lane < Kk) ? d_topk[i*Kk + lane] : i;  // lane 20 -> self
      float z;
      if(lane <= Kk){
        z = si_sm[il] + sj_sm[src];
        z = (z > 0.f) ? z : 0.2f*z;
        if(lane < Kk && src == i) z = -INFINITY;
      } else z = -INFINITY;
      float e = (lane <= Kk) ? __expf(z) : 0.f;   // no max-subtract (z bounded)
      float s = warpSum(e);
      float a = e / s;
      packed = (__float_as_uint(a) & 0xFFFFFE00u) | (unsigned)src;
    }
    float2 acc = make_float2(0.f,0.f);
    #pragma unroll
    for(int e=0; e<=Kk; e++){
      unsigned pk = __shfl_sync(0xffffffffu, packed, e);
      float a  = __uint_as_float(pk & 0xFFFFFE00u);
      int srow = (int)(pk & 511u);
      float2 v = __half22float2(gh_sm[srow*32 + lane]);
      acc.x += a*v.x; acc.y += a*v.y;
    }
    acc.x += bi2.x; acc.y += bi2.y;
    d_aggh[(size_t)(b*512+i)*32 + lane] = __floats2half2_rn(acc.x, acc.y);
    ps.x += acc.x; ps.y += acc.y;
    pq.x += acc.x*acc.x; pq.y += acc.y*acc.y;
  }

  __syncthreads();
  float* rS = sm;          // 16*64
  float* rQ = sm + 1024;   // 16*64
  rS[w*64 + lane*2]   = ps.x;
  rS[w*64 + lane*2+1] = ps.y;
  rQ[w*64 + lane*2]   = pq.x;
  rQ[w*64 + lane*2+1] = pq.y;
  __syncthreads();
  if(t < 64){
    float S=0.f, Q=0.f;
    #pragma unroll
    for(int ww=0; ww<16; ww++){ S += rS[ww*64+t]; Q += rQ[ww*64+t]; }
    d_ps1[t*AGRID + blockIdx.x] = S;
    d_pq1[t*AGRID + blockIdx.x] = Q;
  }
}

// ---- K5: reduce BN partials -> scale/shift. block per channel. ----
__global__ void k_red(const float* __restrict__ ps, const float* __restrict__ pq,
                      int nblk, const float* __restrict__ gamma,
                      const float* __restrict__ beta,
                      float* __restrict__ scale, float* __restrict__ shift){
  __shared__ float shS[8], shQ[8];
  int c = blockIdx.x, t = threadIdx.x;
  float s = 0.f, q = 0.f;
  for(int idx=t; idx<nblk; idx+=256){
    s += ps[c*nblk+idx];
    q += pq[c*nblk+idx];
  }
  s = warpSum(s); q = warpSum(q);
  if((t&31)==0){ shS[t>>5]=s; shQ[t>>5]=q; }
  __syncthreads();
  if(t==0){
    float S=0.f, Q=0.f;
    #pragma unroll
    for(int ww=0; ww<8; ww++){ S+=shS[ww]; Q+=shQ[ww]; }
    float mu  = S * (1.0f/(float)BN);
    float var = Q * (1.0f/(float)BN) - mu*mu;
    float sc  = gamma[c] * rsqrtf(var + 1e-5f);
    scale[c] = sc;
    shift[c] = beta[c] - mu*sc;
  }
}

// ---- K6: BN2 stats only, reads fp16 agg (8MB) ----
// thread t handles channels [(t&7)*8, +8) each iter; 2 iters of uint4 (8 halves)
__global__ void k_h1(const float* __restrict__ embed){
  __shared__ float shp[2048], shq2[2048];
  int t = threadIdx.x;
  int cg = t & 7;              // channel group
  int d0 = cg * 8;
  float sc1[8], sh1[8], psum[8], psq[8];
  #pragma unroll
  for(int c=0; c<8; c++){
    sc1[c] = d_scale1[d0+c]; sh1[c] = d_shift1[d0+c];
    psum[c] = 0.f; psq[c] = 0.f;
  }
  const uint4* agg4 = reinterpret_cast<const uint4*>(d_aggh);
  #pragma unroll
  for(int q=0; q<2; q++){
    int i = blockIdx.x*512 + q*256 + t;    // uint4 index; (i&7)==cg
    int row  = i >> 3;
    int node = row & (Nn-1);
    uint4 av = agg4[i];
    float4 em0 = *reinterpret_cast<const float4*>(&embed[node*64 + d0]);
    float4 em1 = *reinterpret_cast<const float4*>(&embed[node*64 + d0 + 4]);
    const unsigned* au = &av.x;
    float emv[8] = {em0.x,em0.y,em0.z,em0.w,em1.x,em1.y,em1.z,em1.w};
    #pragma unroll
    for(int h=0; h<4; h++){
      float2 a2 = __half22float2(*reinterpret_cast<const __half2*>(&au[h]));
      float r0 = fmaxf(a2.x*sc1[h*2]+sh1[h*2], 0.f)*emv[h*2];
      float r1 = fmaxf(a2.y*sc1[h*2+1]+sh1[h*2+1], 0.f)*emv[h*2+1];
      psum[h*2]   += r0; psq[h*2]   += r0*r0;
      psum[h*2+1] += r1; psq[h*2+1] += r1*r1;
    }
  }
  #pragma unroll
  for(int c=0; c<8; c++){ shp[t*8+c] = psum[c]; shq2[t*8+c] = psq[c]; }
  __syncthreads();
  if(t < 64){
    int group = t >> 3, off = t & 7;   // channel = group*8+off
    float S=0.f, Q=0.f;
    #pragma unroll
    for(int m=0; m<32; m++){
      int th = group + m*8;
      S += shp [th*8+off];
      Q += shq2[th*8+off];
    }
    d_ps2[(group*8+off)*H1_BLOCKS + blockIdx.x] = S;
    d_pq2[(group*8+off)*H1_BLOCKS + blockIdx.x] = Q;
  }
}

// ---- K7: out = relu(bn2(relu(bn1(agg))*embed)) @ out_W + out_b ----
__global__ void k_out(const float* __restrict__ embed,
                      const float* __restrict__ outW, const float* __restrict__ outB,
                      float* __restrict__ out){
  int lane = threadIdx.x & 31, w = threadIdx.x >> 5;
  int sub = lane & 15, half = lane >> 4;
  int row = blockIdx.x*16 + w*2 + half;
  int node = row & (Nn-1);
  uint2 au = *reinterpret_cast<const uint2*>(
      reinterpret_cast<const unsigned*>(d_aggh) + (size_t)row*32 + sub*2);
  float2 a01 = __half22float2(*reinterpret_cast<const __half2*>(&au.x));
  float2 a23 = __half22float2(*reinterpret_cast<const __half2*>(&au.y));
  float4 em  = *reinterpret_cast<const float4*>(&embed[node*64 + sub*4]);
  float4 s1  = *reinterpret_cast<const float4*>(&d_scale1[sub*4]);
  float4 h1_ = *reinterpret_cast<const float4*>(&d_shift1[sub*4]);
  float4 s2  = *reinterpret_cast<const float4*>(&d_scale2[sub*4]);
  float4 h2_ = *reinterpret_cast<const float4*>(&d_shift2[sub*4]);
  float4 ow  = *reinterpret_cast<const float4*>(&outW[sub*4]);
  float hx = fmaxf(a01.x*s1.x+h1_.x,0.f)*em.x;
  float hy = fmaxf(a01.y*s1.y+h1_.y,0.f)*em.y;
  float hz = fmaxf(a23.x*s1.z+h1_.z,0.f)*em.z;
  float hw = fmaxf(a23.y*s1.w+h1_.w,0.f)*em.w;
  float p = fmaxf(hx*s2.x+h2_.x,0.f)*ow.x + fmaxf(hy*s2.y+h2_.y,0.f)*ow.y
          + fmaxf(hz*s2.z+h2_.z,0.f)*ow.z + fmaxf(hw*s2.w+h2_.w,0.f)*ow.w;
  #pragma unroll
  for(int o=8; o; o>>=1) p += __shfl_xor_sync(0xffffffffu, p, o);
  if(sub==0) out[row] = p + outB[0];
}

extern "C" void kernel_launch(void* const* d_in, const int* in_sizes, int n_in,
                              void* d_out, int out_size){
  int iData, iEmbed, iW, iAtI, iAtJ, iAemI, iAemJ, iBias, iG1, iB1, iG2, iB2, iOW, iOB;
  if(n_in >= 15 && in_sizes[1] == 2048){
    iData=0; iEmbed=2; iW=3; iAtI=4; iAtJ=5; iAemI=6; iAemJ=7; iBias=8;
    iG1=9; iB1=10; iG2=11; iB2=12; iOW=13; iOB=14;
  } else {
    iData=0; iEmbed=1; iW=2; iAtI=3; iAtJ=4; iAemI=5; iAemJ=6; iBias=7;
    iG1=8; iB1=9; iG2=10; iB2=11; iOW=12; iOB=13;
  }
  const float* data  = (const float*)d_in[iData];
  const float* embed = (const float*)d_in[iEmbed];
  const float* W     = (const float*)d_in[iW];
  const float* atI   = (const float*)d_in[iAtI];
  const float* atJ   = (const float*)d_in[iAtJ];
  const float* aemI  = (const float*)d_in[iAemI];
  const float* aemJ  = (const float*)d_in[iAemJ];
  const float* bias  = (const float*)d_in[iBias];
  const float* g1    = (const float*)d_in[iG1];
  const float* b1    = (const float*)d_in[iB1];
  const float* g2    = (const float*)d_in[iG2];
  const float* b2    = (const float*)d_in[iB2];
  const float* outW  = (const float*)d_in[iOW];
  const float* outB  = (const float*)d_in[iOB];
  float* out = (float*)d_out;

  float *sc1, *sh1, *sc2, *sh2, *ps1, *pq1, *ps2, *pq2;
  cudaGetSymbolAddress((void**)&sc1, d_scale1);
  cudaGetSymbolAddress((void**)&sh1, d_shift1);
  cudaGetSymbolAddress((void**)&sc2, d_scale2);
  cudaGetSymbolAddress((void**)&sh2, d_shift2);
  cudaGetSymbolAddress((void**)&ps1, d_ps1);
  cudaGetSymbolAddress((void**)&pq1, d_pq1);
  cudaGetSymbolAddress((void**)&ps2, d_ps2);
  cudaGetSymbolAddress((void**)&pq2, d_pq2);

  cudaFuncSetAttribute(k_attn, cudaFuncAttributeMaxDynamicSharedMemorySize, ATTN_SMEM_BYTES);
  cudaFuncSetAttribute(k_gemm, cudaFuncAttributeMaxDynamicSharedMemorySize, GEMM_SMEM);

  k_embed<<<64, 256>>>(embed, aemI, aemJ);
  k_topk <<<64, 256>>>();
  k_gemm <<<BN/128, 256, GEMM_SMEM>>>(data, W, atI, atJ);
  k_attn <<<AGRID, 512, ATTN_SMEM_BYTES>>>(bias);
  k_red  <<<64, 256>>>(ps1, pq1, AGRID, g1, b1, sc1, sh1);
  k_h1   <<<H1_BLOCKS, 256>>>(embed);
  k_red  <<<64, 256>>>(ps2, pq2, H1_BLOCKS, g2, b2, sc2, sh2);
  k_out  <<<BN/16, 256>>>(embed, outW, outB, out);
}

// round 12
// speedup vs baseline: 1.0466x; 1.0466x over previous
#include <cuda_runtime.h>
#include <cuda_fp16.h>
#include <mma.h>
#include <math.h>

using namespace nvcuda;

#define Bsz 128
#define Nn  512
#define Ff  64
#define Dd  64
#define Kk  20
#define BN  (Bsz*Nn)          // 65536
#define NELEM (BN*Dd)         // 4194304
#define AGRID 512             // attn: 4 blocks per batch
#define TGRID 512             // tail grid (must be <= resident capacity)

// ---------------- device scratch (no allocations allowed) ----------------
__device__ __half2 d_gh2[NELEM/2];        // g in fp16, [row][64]
__device__ float d_agg[NELEM];            // agg fp32
__device__ float d_si[BN];
__device__ float d_sj[BN];
__device__ float d_eai[Nn];
__device__ float d_eaj[Nn];
__device__ int   d_topk[Nn*Kk];
__device__ float d_ps1[64*AGRID];         // channel-major BN1 partials
__device__ float d_pq1[64*AGRID];
__device__ float d_ps2[64*TGRID];         // channel-major BN2 partials
__device__ float d_pq2[64*TGRID];
__device__ float d_scale1[64], d_shift1[64], d_scale2[64], d_shift2[64];
__device__ unsigned g_bar;                // monotonic grid-barrier counter

__device__ __forceinline__ float warpSum(float v){
  #pragma unroll
  for(int o=16;o;o>>=1) v += __shfl_xor_sync(0xffffffffu, v, o);
  return v;
}

// ---- K1: fused embed-normalize + eai/eaj + warp-per-node topk ----
__global__ void k_pre(const float* __restrict__ embed,
                      const float* __restrict__ aemi,
                      const float* __restrict__ aemj){
  __shared__ float tile[64*68];
  __shared__ float srows[8*68];
  __shared__ float invn[64];
  int t = threadIdx.x, w = t>>5, lane = t&31;
  int node = blockIdx.x*8 + w;

  // own 8 rows raw
  if(t < 128){
    int r = t >> 4, c4 = t & 15;
    float4 v = reinterpret_cast<const float4*>(embed)[(blockIdx.x*8 + r)*16 + c4];
    *reinterpret_cast<float4*>(&srows[r*68 + c4*4]) = v;
  }
  __syncthreads();
  // normalize own row + eai/eaj (raw embed dots)
  {
    float v0 = srows[w*68+lane], v1 = srows[w*68+32+lane];
    float ss = warpSum(v0*v0 + v1*v1);
    float inv = 1.0f/(sqrtf(ss)+1e-12f);
    float si = warpSum(v0*aemi[lane] + v1*aemi[lane+32]);
    float sj = warpSum(v0*aemj[lane] + v1*aemj[lane+32]);
    if(lane==0){ d_eai[node]=si; d_eaj[node]=sj; }
    srows[w*68+lane]    = v0*inv;
    srows[w*68+32+lane] = v1*inv;
  }

  float sims[16];
  #pragma unroll
  for(int chunk=0; chunk<8; chunk++){
    __syncthreads();
    // load raw embed chunk (64 rows)
    #pragma unroll
    for(int q=0; q<4; q++){
      int idx = t + q*256;
      int r = idx >> 4, c4 = idx & 15;
      float4 v = reinterpret_cast<const float4*>(embed)[(chunk*64 + r)*16 + c4];
      *reinterpret_cast<float4*>(&tile[r*68 + c4*4]) = v;
    }
    __syncthreads();
    if(t < 64){
      const float* rr = &tile[t*68];
      float ss = 0.f;
      #pragma unroll
      for(int q=0; q<16; q++){
        float4 v = *reinterpret_cast<const float4*>(&rr[q*4]);
        ss += v.x*v.x + v.y*v.y + v.z*v.z + v.w*v.w;
      }
      invn[t] = 1.0f/(sqrtf(ss)+1e-12f);
    }
    __syncthreads();
    #pragma unroll
    for(int q=0; q<4; q++){
      int idx = t + q*256;
      int r = idx >> 4;
      float inv = invn[r];
      float4* p = reinterpret_cast<float4*>(&tile[r*68 + (idx&15)*4]);
      float4 v = *p;
      v.x*=inv; v.y*=inv; v.z*=inv; v.w*=inv;
      *p = v;
    }
    __syncthreads();
    const float* sr = &srows[w*68];
    float a0 = 0.f, a1 = 0.f;
    #pragma unroll
    for(int kk=0; kk<64; kk+=4){
      float4 s4 = *reinterpret_cast<const float4*>(&sr[kk]);
      float4 e0 = *reinterpret_cast<const float4*>(&tile[lane*68+kk]);
      float4 e1 = *reinterpret_cast<const float4*>(&tile[(lane+32)*68+kk]);
      a0 += s4.x*e0.x + s4.y*e0.y + s4.z*e0.z + s4.w*e0.w;
      a1 += s4.x*e1.x + s4.y*e1.y + s4.z*e1.z + s4.w*e1.w;
    }
    sims[chunk*2]   = a0;
    sims[chunk*2+1] = a1;
  }

  for(int sel=0; sel<Kk; sel++){
    float bv = -INFINITY; int bj = 0x3fffffff;
    #pragma unroll
    for(int s=0; s<16; s++){
      float v = sims[s];
      int j = (s>>1)*64 + (s&1)*32 + lane;
      if(v > bv || (v == bv && j < bj)){ bv = v; bj = j; }
    }
    #pragma unroll
    for(int o=16; o; o>>=1){
      float ov = __shfl_xor_sync(0xffffffffu, bv, o);
      int   oj = __shfl_xor_sync(0xffffffffu, bj, o);
      if(ov > bv || (ov == bv && oj < bj)){ bv = ov; bj = oj; }
    }
    if(lane==0) d_topk[node*Kk+sel] = bj;
    int wslot = ((bj>>6)<<1) | ((bj>>5)&1);
    bool own = ((bj & 31) == lane);
    #pragma unroll
    for(int s=0; s<16; s++) if(own && s==wslot) sims[s] = -INFINITY;
  }
}

// ---- K2: g = x @ W_lin via WMMA (half inputs, fp32 accum), + s_i/s_j ----
#define GS_XH 0
#define GS_WH 18432
#define GS_CS 27648
#define GEMM_SMEM (27648 + 128*68*4)   // 62464

__global__ void __launch_bounds__(256,3) k_gemm(const float* __restrict__ x,
                       const float* __restrict__ W,
                       const float* __restrict__ ati, const float* __restrict__ atj){
  extern __shared__ char gsm[];
  __half* Xh = reinterpret_cast<__half*>(gsm + GS_XH);
  __half* Wh = reinterpret_cast<__half*>(gsm + GS_WH);
  float*  Cs = reinterpret_cast<float*>(gsm + GS_CS);
  __shared__ float s_si[128][2], s_sj[128][2];

  int t = threadIdx.x;

  const float2* W2 = reinterpret_cast<const float2*>(W);
  #pragma unroll
  for(int q=0; q<8; q++){
    int idx = q*256 + t;
    float2 wv = W2[idx];
    int r = idx >> 5, c2 = idx & 31;
    reinterpret_cast<__half2*>(Wh + r*72)[c2] = __floats2half2_rn(wv.x, wv.y);
  }
  const float2* X2 = reinterpret_cast<const float2*>(x + (size_t)blockIdx.x*128*64);
  #pragma unroll
  for(int q=0; q<16; q++){
    int idx = q*256 + t;
    float2 xv = X2[idx];
    int r = idx >> 5, c2 = idx & 31;
    reinterpret_cast<__half2*>(Xh + r*72)[c2] = __floats2half2_rn(xv.x, xv.y);
  }
  __syncthreads();

  int w = t >> 5;
  wmma::fragment<wmma::accumulator,16,16,16,float> acc[4];
  #pragma unroll
  for(int n=0; n<4; n++) wmma::fill_fragment(acc[n], 0.0f);
  #pragma unroll
  for(int k=0; k<4; k++){
    wmma::fragment<wmma::matrix_a,16,16,16,__half,wmma::row_major> fa;
    wmma::load_matrix_sync(fa, Xh + (w*16)*72 + k*16, 72);
    #pragma unroll
    for(int n=0; n<4; n++){
      wmma::fragment<wmma::matrix_b,16,16,16,__half,wmma::row_major> fb;
      wmma::load_matrix_sync(fb, Wh + (k*16)*72 + n*16, 72);
      wmma::mma_sync(acc[n], fa, fb, acc[n]);
    }
  }
  #pragma unroll
  for(int n=0; n<4; n++)
    wmma::store_matrix_sync(Cs + (w*16)*68 + n*16, acc[n], 68, wmma::mem_row_major);
  __syncthreads();

  int row = t >> 1, hf = t & 1;
  const float* crow = Cs + row*68 + hf*32;
  float si = 0.f, sj = 0.f;
  union { __half2 h2[16]; uint4 u4[4]; } cv;
  #pragma unroll
  for(int q=0; q<8; q++){
    float4 c4 = *reinterpret_cast<const float4*>(crow + q*4);
    float4 av = *reinterpret_cast<const float4*>(ati + hf*32 + q*4);
    float4 aw = *reinterpret_cast<const float4*>(atj + hf*32 + q*4);
    si += c4.x*av.x + c4.y*av.y + c4.z*av.z + c4.w*av.w;
    sj += c4.x*aw.x + c4.y*aw.y + c4.z*aw.z + c4.w*aw.w;
    cv.h2[q*2]   = __floats2half2_rn(c4.x, c4.y);
    cv.h2[q*2+1] = __floats2half2_rn(c4.z, c4.w);
  }
  uint4* ghp = reinterpret_cast<uint4*>(d_gh2);
  int grow = blockIdx.x*128 + row;
  #pragma unroll
  for(int q=0; q<4; q++) ghp[(size_t)grow*8 + hf*4 + q] = cv.u4[q];
  s_si[row][hf] = si; s_sj[row][hf] = sj;
  __syncthreads();
  if(t < 128){
    int gr = blockIdx.x*128 + t;
    int node = gr & (Nn-1);
    d_si[gr] = s_si[t][0] + s_si[t][1] + d_eai[node];
    d_sj[gr] = s_sj[t][0] + s_sj[t][1] + d_eaj[node];
  }
}

// ---- K3: 4 blocks/batch, 512 threads; fp16 g slice in smem; fp32 agg out ----
#define ATTN_SMEM_FLOATS (16384 + 512 + 128)   // gh(64KB) + sj + si
#define ATTN_SMEM_BYTES  (ATTN_SMEM_FLOATS*4)

__global__ void __launch_bounds__(512,3) k_attn(const float* __restrict__ gnn_bias){
  extern __shared__ float sm[];
  __half2* gh_sm = reinterpret_cast<__half2*>(sm);   // [src*32 + lane]
  float* sj_sm = sm + 16384;   // 512
  float* si_sm = sm + 16896;   // 128 (this block's rows)

  int t = threadIdx.x, lane = t & 31, w = t >> 5;
  int b  = blockIdx.x >> 2;
  int row0 = (blockIdx.x & 3) * 128;

  const uint4* s4 = reinterpret_cast<const uint4*>(d_gh2 + (size_t)b*16384);
  uint4* dst4 = reinterpret_cast<uint4*>(sm);
  #pragma unroll
  for(int q=0; q<8; q++) dst4[q*512+t] = s4[q*512+t];
  sj_sm[t] = d_sj[b*512+t];
  if(t < 128) si_sm[t] = d_si[b*512 + row0 + t];
  __syncthreads();

  float2 bi2 = reinterpret_cast<const float2*>(gnn_bias)[lane];
  float2 ps = make_float2(0.f,0.f), pq = make_float2(0.f,0.f);

  for(int it=0; it<8; it++){
    int il = w*8 + it;            // local row 0..127
    int i  = row0 + il;           // node in batch
    unsigned packed;
    {
      int src = (lane < Kk) ? d_topk[i*Kk + lane] : i;  // lane 20 -> self
      float z;
      if(lane <= Kk){
        z = si_sm[il] + sj_sm[src];
        z = (z > 0.f) ? z : 0.2f*z;
        if(lane < Kk && src == i) z = -INFINITY;
      } else z = -INFINITY;
      float e = (lane <= Kk) ? __expf(z) : 0.f;   // no max-subtract (z bounded)
      float s = warpSum(e);
      float a = e / s;
      packed = (__float_as_uint(a) & 0xFFFFFE00u) | (unsigned)src;
    }
    float2 acc = make_float2(0.f,0.f);
    #pragma unroll
    for(int e=0; e<=Kk; e++){
      unsigned pk = __shfl_sync(0xffffffffu, packed, e);
      float a  = __uint_as_float(pk & 0xFFFFFE00u);
      int srow = (int)(pk & 511u);
      float2 v = __half22float2(gh_sm[srow*32 + lane]);
      acc.x += a*v.x; acc.y += a*v.y;
    }
    acc.x += bi2.x; acc.y += bi2.y;
    reinterpret_cast<float2*>(&d_agg[(size_t)(b*512+i)*64])[lane] = acc;
    ps.x += acc.x; ps.y += acc.y;
    pq.x += acc.x*acc.x; pq.y += acc.y*acc.y;
  }

  __syncthreads();
  float* rS = sm;          // 16*64
  float* rQ = sm + 1024;   // 16*64
  rS[w*64 + lane*2]   = ps.x;
  rS[w*64 + lane*2+1] = ps.y;
  rQ[w*64 + lane*2]   = pq.x;
  rQ[w*64 + lane*2+1] = pq.y;
  __syncthreads();
  if(t < 64){
    float S=0.f, Q=0.f;
    #pragma unroll
    for(int ww=0; ww<16; ww++){ S += rS[ww*64+t]; Q += rQ[ww*64+t]; }
    d_ps1[t*AGRID + blockIdx.x] = S;
    d_pq1[t*AGRID + blockIdx.x] = Q;
  }
}

// ---- K4: fused tail: red1 -> BN2 stats -> red2 -> out (persistent, 3 grid barriers) ----
__device__ __forceinline__ void gridBarrier(){
  __threadfence();
  __syncthreads();
  if(threadIdx.x == 0){
    unsigned old = atomicAdd(&g_bar, 1u);
    unsigned target = (old/(unsigned)TGRID + 1u) * (unsigned)TGRID;
    while(((*(volatile unsigned*)&g_bar) - target) & 0x80000000u) __nanosleep(32);
  }
  __syncthreads();
}

__device__ __forceinline__ void reduceScale(const float* __restrict__ ps,
                                            const float* __restrict__ pq,
                                            const float* __restrict__ gamma,
                                            const float* __restrict__ beta,
                                            float* __restrict__ scale,
                                            float* __restrict__ shift,
                                            float* shS, float* shQ){
  int c = blockIdx.x, t = threadIdx.x;
  float s = ps[c*TGRID + t] + ps[c*TGRID + t + 256];
  float q = pq[c*TGRID + t] + pq[c*TGRID + t + 256];
  s = warpSum(s); q = warpSum(q);
  if((t&31)==0){ shS[t>>5]=s; shQ[t>>5]=q; }
  __syncthreads();
  if(t==0){
    float S=0.f, Q=0.f;
    #pragma unroll
    for(int ww=0; ww<8; ww++){ S+=shS[ww]; Q+=shQ[ww]; }
    float mu  = S * (1.0f/(float)BN);
    float var = Q * (1.0f/(float)BN) - mu*mu;
    float sc  = gamma[c] * rsqrtf(var + 1e-5f);
    scale[c] = sc;
    shift[c] = beta[c] - mu*sc;
  }
}

__global__ void __launch_bounds__(256,4) k_tail(const float* __restrict__ embed,
                      const float* __restrict__ g1, const float* __restrict__ b1,
                      const float* __restrict__ g2, const float* __restrict__ b2,
                      const float* __restrict__ outW, const float* __restrict__ outB,
                      float* __restrict__ out){
  __shared__ float shp[1024], shq2[1024];
  int t = threadIdx.x;

  // phase 1: BN1 scale/shift (blocks 0..63; attn wrote d_ps1[64][AGRID=512])
  if(blockIdx.x < 64)
    reduceScale(d_ps1, d_pq1, g1, b1, d_scale1, d_shift1, shp, shq2);
  gridBarrier();

  // phase 2: BN2 stats over h1 = relu(bn1(agg))*embed ; 2048 float4 per block
  {
    int d0 = (t & 15) * 4;
    float4 sc1 = *reinterpret_cast<const float4*>(&d_scale1[d0]);
    float4 sh1 = *reinterpret_cast<const float4*>(&d_shift1[d0]);
    float4 psum = make_float4(0.f,0.f,0.f,0.f);
    float4 psq  = make_float4(0.f,0.f,0.f,0.f);
    #pragma unroll
    for(int q=0; q<8; q++){
      int i = blockIdx.x*2048 + q*256 + t;   // (i&15)==(t&15)
      int row  = i >> 4;
      int node = row & (Nn-1);
      float4 a  = reinterpret_cast<const float4*>(d_agg)[i];
      float4 em = reinterpret_cast<const float4*>(embed)[node*16 + (t&15)];
      float4 r;
      r.x = fmaxf(a.x*sc1.x+sh1.x, 0.f)*em.x;
      r.y = fmaxf(a.y*sc1.y+sh1.y, 0.f)*em.y;
      r.z = fmaxf(a.z*sc1.z+sh1.z, 0.f)*em.z;
      r.w = fmaxf(a.w*sc1.w+sh1.w, 0.f)*em.w;
      psum.x += r.x; psum.y += r.y; psum.z += r.z; psum.w += r.w;
      psq.x += r.x*r.x; psq.y += r.y*r.y; psq.z += r.z*r.z; psq.w += r.w*r.w;
    }
    __syncthreads();   // shp reuse safety
    shp[t*4+0]=psum.x; shp[t*4+1]=psum.y; shp[t*4+2]=psum.z; shp[t*4+3]=psum.w;
    shq2[t*4+0]=psq.x; shq2[t*4+1]=psq.y; shq2[t*4+2]=psq.z; shq2[t*4+3]=psq.w;
    __syncthreads();
    if(t < 64){
      int gi = t >> 2, comp = t & 3;
      float S=0.f, Q=0.f;
      #pragma unroll
      for(int m=0; m<16; m++){
        S += shp [(gi + m*16)*4 + comp];
        Q += shq2[(gi + m*16)*4 + comp];
      }
      d_ps2[t*TGRID + blockIdx.x] = S;
      d_pq2[t*TGRID + blockIdx.x] = Q;
    }
  }
  gridBarrier();

  // phase 3: BN2 scale/shift
  if(blockIdx.x < 64)
    reduceScale(d_ps2, d_pq2, g2, b2, d_scale2, d_shift2, shp, shq2);
  gridBarrier();

  // phase 4: out = relu(bn2(relu(bn1(agg))*embed)) @ out_W + out_b
  {
    int sub = t & 15;
    float4 s1  = *reinterpret_cast<const float4*>(&d_scale1[sub*4]);
    float4 h1_ = *reinterpret_cast<const float4*>(&d_shift1[sub*4]);
    float4 s2  = *reinterpret_cast<const float4*>(&d_scale2[sub*4]);
    float4 h2_ = *reinterpret_cast<const float4*>(&d_shift2[sub*4]);
    float4 ow  = *reinterpret_cast<const float4*>(&outW[sub*4]);
    float ob = outB[0];
    #pragma unroll
    for(int it=0; it<8; it++){
      int row  = blockIdx.x*128 + it*16 + (t >> 4);
      int node = row & (Nn-1);
      float4 a  = *reinterpret_cast<const float4*>(&d_agg[(size_t)row*64 + sub*4]);
      float4 em = *reinterpret_cast<const float4*>(&embed[node*64 + sub*4]);
      float hx = fmaxf(a.x*s1.x+h1_.x,0.f)*em.x;
      float hy = fmaxf(a.y*s1.y+h1_.y,0.f)*em.y;
      float hz = fmaxf(a.z*s1.z+h1_.z,0.f)*em.z;
      float hw = fmaxf(a.w*s1.w+h1_.w,0.f)*em.w;
      float p = fmaxf(hx*s2.x+h2_.x,0.f)*ow.x + fmaxf(hy*s2.y+h2_.y,0.f)*ow.y
              + fmaxf(hz*s2.z+h2_.z,0.f)*ow.z + fmaxf(hw*s2.w+h2_.w,0.f)*ow.w;
      #pragma unroll
      for(int o=8; o; o>>=1) p += __shfl_xor_sync(0xffffffffu, p, o);
      if(sub==0) out[row] = p + ob;
    }
  }
}

extern "C" void kernel_launch(void* const* d_in, const int* in_sizes, int n_in,
                              void* d_out, int out_size){
  int iData, iEmbed, iW, iAtI, iAtJ, iAemI, iAemJ, iBias, iG1, iB1, iG2, iB2, iOW, iOB;
  if(n_in >= 15 && in_sizes[1] == 2048){
    iData=0; iEmbed=2; iW=3; iAtI=4; iAtJ=5; iAemI=6; iAemJ=7; iBias=8;
    iG1=9; iB1=10; iG2=11; iB2=12; iOW=13; iOB=14;
  } else {
    iData=0; iEmbed=1; iW=2; iAtI=3; iAtJ=4; iAemI=5; iAemJ=6; iBias=7;
    iG1=8; iB1=9; iG2=10; iB2=11; iOW=12; iOB=13;
  }
  const float* data  = (const float*)d_in[iData];
  const float* embed = (const float*)d_in[iEmbed];
  const float* W     = (const float*)d_in[iW];
  const float* atI   = (const float*)d_in[iAtI];
  const float* atJ   = (const float*)d_in[iAtJ];
  const float* aemI  = (const float*)d_in[iAemI];
  const float* aemJ  = (const float*)d_in[iAemJ];
  const float* bias  = (const float*)d_in[iBias];
  const float* g1    = (const float*)d_in[iG1];
  const float* b1    = (const float*)d_in[iB1];
  const float* g2    = (const float*)d_in[iG2];
  const float* b2    = (const float*)d_in[iB2];
  const float* outW  = (const float*)d_in[iOW];
  const float* outB  = (const float*)d_in[iOB];
  float* out = (float*)d_out;

  cudaFuncSetAttribute(k_attn, cudaFuncAttributeMaxDynamicSharedMemorySize, ATTN_SMEM_BYTES);
  cudaFuncSetAttribute(k_gemm, cudaFuncAttributeMaxDynamicSharedMemorySize, GEMM_SMEM);

  k_pre  <<<64, 256>>>(embed, aemI, aemJ);
  k_gemm <<<BN/128, 256, GEMM_SMEM>>>(data, W, atI, atJ);
  k_attn <<<AGRID, 512, ATTN_SMEM_BYTES>>>(bias);
  k_tail <<<TGRID, 256>>>(embed, g1, b1, g2, b2, outW, outB, out);
}

// round 13
// speedup vs baseline: 1.1418x; 1.0910x over previous
#include <cuda_runtime.h>
#include <cuda_fp16.h>
#include <mma.h>
#include <math.h>

using namespace nvcuda;

#define Bsz 128
#define Nn  512
#define Ff  64
#define Dd  64
#define Kk  20
#define BN  (Bsz*Nn)          // 65536
#define NELEM (BN*Dd)         // 4194304
#define AGRID 512             // attn: 4 blocks per batch
#define TGRID 512             // tail grid

// ---------------- device scratch (no allocations allowed) ----------------
__device__ __half2 d_gh2[NELEM/2];        // g in fp16, [row][64]
__device__ float d_agg[NELEM];            // agg fp32
__device__ float d_si[BN];
__device__ float d_sj[BN];
__device__ float d_eai[Nn];
__device__ float d_eaj[Nn];
__device__ int   d_topk[Nn*Kk];
__device__ float d_ps1[64*AGRID];         // channel-major BN1 partials
__device__ float d_pq1[64*AGRID];
__device__ float d_ps2[64*TGRID];         // channel-major BN2 partials
__device__ float d_pq2[64*TGRID];
__device__ float d_scale1[64], d_shift1[64], d_scale2[64], d_shift2[64];
__device__ unsigned g_bar;                // monotonic grid-barrier counter

__device__ __forceinline__ float warpSum(float v){
  #pragma unroll
  for(int o=16;o;o>>=1) v += __shfl_xor_sync(0xffffffffu, v, o);
  return v;
}

// ==== fused work kernel: blocks 0-63 -> pre(topk), blocks 64-575 -> gemm ====
#define GS_XH 0
#define GS_WH 18432
#define GS_CS 27648
#define WORK_SMEM (27648 + 128*68*4)   // 62464 bytes (gemm layout; pre fits inside)

__device__ void pre_body(char* gsm, const float* __restrict__ embed,
                         const float* __restrict__ aemi,
                         const float* __restrict__ aemj){
  float* tile  = reinterpret_cast<float*>(gsm);            // 64*68
  float* srows = tile + 64*68;                             // 8*68
  float* invn  = srows + 8*68;                             // 64
  int t = threadIdx.x, w = t>>5, lane = t&31;
  int node = blockIdx.x*8 + w;

  if(t < 128){
    int r = t >> 4, c4 = t & 15;
    float4 v = reinterpret_cast<const float4*>(embed)[(blockIdx.x*8 + r)*16 + c4];
    *reinterpret_cast<float4*>(&srows[r*68 + c4*4]) = v;
  }
  __syncthreads();
  {
    float v0 = srows[w*68+lane], v1 = srows[w*68+32+lane];
    float ss = warpSum(v0*v0 + v1*v1);
    float inv = 1.0f/(sqrtf(ss)+1e-12f);
    float si = warpSum(v0*aemi[lane] + v1*aemi[lane+32]);
    float sj = warpSum(v0*aemj[lane] + v1*aemj[lane+32]);
    if(lane==0){ d_eai[node]=si; d_eaj[node]=sj; }
    srows[w*68+lane]    = v0*inv;
    srows[w*68+32+lane] = v1*inv;
  }

  float sims[16];
  #pragma unroll
  for(int chunk=0; chunk<8; chunk++){
    __syncthreads();
    #pragma unroll
    for(int q=0; q<4; q++){
      int idx = t + q*256;
      int r = idx >> 4, c4 = idx & 15;
      float4 v = reinterpret_cast<const float4*>(embed)[(chunk*64 + r)*16 + c4];
      *reinterpret_cast<float4*>(&tile[r*68 + c4*4]) = v;
    }
    __syncthreads();
    if(t < 64){
      const float* rr = &tile[t*68];
      float ss = 0.f;
      #pragma unroll
      for(int q=0; q<16; q++){
        float4 v = *reinterpret_cast<const float4*>(&rr[q*4]);
        ss += v.x*v.x + v.y*v.y + v.z*v.z + v.w*v.w;
      }
      invn[t] = 1.0f/(sqrtf(ss)+1e-12f);
    }
    __syncthreads();
    #pragma unroll
    for(int q=0; q<4; q++){
      int idx = t + q*256;
      int r = idx >> 4;
      float inv = invn[r];
      float4* p = reinterpret_cast<float4*>(&tile[r*68 + (idx&15)*4]);
      float4 v = *p;
      v.x*=inv; v.y*=inv; v.z*=inv; v.w*=inv;
      *p = v;
    }
    __syncthreads();
    const float* sr = &srows[w*68];
    float a0 = 0.f, a1 = 0.f;
    #pragma unroll
    for(int kk=0; kk<64; kk+=4){
      float4 s4 = *reinterpret_cast<const float4*>(&sr[kk]);
      float4 e0 = *reinterpret_cast<const float4*>(&tile[lane*68+kk]);
      float4 e1 = *reinterpret_cast<const float4*>(&tile[(lane+32)*68+kk]);
      a0 += s4.x*e0.x + s4.y*e0.y + s4.z*e0.z + s4.w*e0.w;
      a1 += s4.x*e1.x + s4.y*e1.y + s4.z*e1.z + s4.w*e1.w;
    }
    sims[chunk*2]   = a0;
    sims[chunk*2+1] = a1;
  }

  for(int sel=0; sel<Kk; sel++){
    float bv = -INFINITY; int bj = 0x3fffffff;
    #pragma unroll
    for(int s=0; s<16; s++){
      float v = sims[s];
      int j = (s>>1)*64 + (s&1)*32 + lane;
      if(v > bv || (v == bv && j < bj)){ bv = v; bj = j; }
    }
    #pragma unroll
    for(int o=16; o; o>>=1){
      float ov = __shfl_xor_sync(0xffffffffu, bv, o);
      int   oj = __shfl_xor_sync(0xffffffffu, bj, o);
      if(ov > bv || (ov == bv && oj < bj)){ bv = ov; bj = oj; }
    }
    if(lane==0) d_topk[node*Kk+sel] = bj;
    int wslot = ((bj>>6)<<1) | ((bj>>5)&1);
    bool own = ((bj & 31) == lane);
    #pragma unroll
    for(int s=0; s<16; s++) if(own && s==wslot) sims[s] = -INFINITY;
  }
}

__device__ void gemm_body(char* gsm, int blk, const float* __restrict__ x,
                          const float* __restrict__ W,
                          const float* __restrict__ ati, const float* __restrict__ atj){
  __half* Xh = reinterpret_cast<__half*>(gsm + GS_XH);
  __half* Wh = reinterpret_cast<__half*>(gsm + GS_WH);
  float*  Cs = reinterpret_cast<float*>(gsm + GS_CS);
  __shared__ float s_si[128][2], s_sj[128][2];

  int t = threadIdx.x;

  const float2* W2 = reinterpret_cast<const float2*>(W);
  #pragma unroll
  for(int q=0; q<8; q++){
    int idx = q*256 + t;
    float2 wv = W2[idx];
    int r = idx >> 5, c2 = idx & 31;
    reinterpret_cast<__half2*>(Wh + r*72)[c2] = __floats2half2_rn(wv.x, wv.y);
  }
  const float2* X2 = reinterpret_cast<const float2*>(x + (size_t)blk*128*64);
  #pragma unroll
  for(int q=0; q<16; q++){
    int idx = q*256 + t;
    float2 xv = X2[idx];
    int r = idx >> 5, c2 = idx & 31;
    reinterpret_cast<__half2*>(Xh + r*72)[c2] = __floats2half2_rn(xv.x, xv.y);
  }
  __syncthreads();

  int w = t >> 5;
  wmma::fragment<wmma::accumulator,16,16,16,float> acc[4];
  #pragma unroll
  for(int n=0; n<4; n++) wmma::fill_fragment(acc[n], 0.0f);
  #pragma unroll
  for(int k=0; k<4; k++){
    wmma::fragment<wmma::matrix_a,16,16,16,__half,wmma::row_major> fa;
    wmma::load_matrix_sync(fa, Xh + (w*16)*72 + k*16, 72);
    #pragma unroll
    for(int n=0; n<4; n++){
      wmma::fragment<wmma::matrix_b,16,16,16,__half,wmma::row_major> fb;
      wmma::load_matrix_sync(fb, Wh + (k*16)*72 + n*16, 72);
      wmma::mma_sync(acc[n], fa, fb, acc[n]);
    }
  }
  #pragma unroll
  for(int n=0; n<4; n++)
    wmma::store_matrix_sync(Cs + (w*16)*68 + n*16, acc[n], 68, wmma::mem_row_major);
  __syncthreads();

  int row = t >> 1, hf = t & 1;
  const float* crow = Cs + row*68 + hf*32;
  float si = 0.f, sj = 0.f;
  union { __half2 h2[16]; uint4 u4[4]; } cv;
  #pragma unroll
  for(int q=0; q<8; q++){
    float4 c4 = *reinterpret_cast<const float4*>(crow + q*4);
    float4 av = *reinterpret_cast<const float4*>(ati + hf*32 + q*4);
    float4 aw = *reinterpret_cast<const float4*>(atj + hf*32 + q*4);
    si += c4.x*av.x + c4.y*av.y + c4.z*av.z + c4.w*av.w;
    sj += c4.x*aw.x + c4.y*aw.y + c4.z*aw.z + c4.w*aw.w;
    cv.h2[q*2]   = __floats2half2_rn(c4.x, c4.y);
    cv.h2[q*2+1] = __floats2half2_rn(c4.z, c4.w);
  }
  uint4* ghp = reinterpret_cast<uint4*>(d_gh2);
  int grow = blk*128 + row;
  #pragma unroll
  for(int q=0; q<4; q++) ghp[(size_t)grow*8 + hf*4 + q] = cv.u4[q];
  s_si[row][hf] = si; s_sj[row][hf] = sj;
  __syncthreads();
  if(t < 128){
    int gr = blk*128 + t;
    d_si[gr] = s_si[t][0] + s_si[t][1];   // eai added in k_attn
    d_sj[gr] = s_sj[t][0] + s_sj[t][1];
  }
}

__global__ void __launch_bounds__(256,3) k_work(const float* __restrict__ x,
                      const float* __restrict__ W,
                      const float* __restrict__ ati, const float* __restrict__ atj,
                      const float* __restrict__ embed,
                      const float* __restrict__ aemi, const float* __restrict__ aemj){
  extern __shared__ char gsm[];
  if(blockIdx.x < 64) pre_body(gsm, embed, aemi, aemj);
  else                gemm_body(gsm, blockIdx.x - 64, x, W, ati, atj);
}

// ---- K2: 4 blocks/batch, 512 threads; fp16 g slice in smem; fp32 agg out ----
#define ATTN_SMEM_FLOATS (16384 + 512 + 128)   // gh(64KB) + sj + si
#define ATTN_SMEM_BYTES  (ATTN_SMEM_FLOATS*4)

__global__ void __launch_bounds__(512,3) k_attn(const float* __restrict__ gnn_bias){
  extern __shared__ float sm[];
  __half2* gh_sm = reinterpret_cast<__half2*>(sm);   // [src*32 + lane]
  float* sj_sm = sm + 16384;   // 512
  float* si_sm = sm + 16896;   // 128 (this block's rows)

  int t = threadIdx.x, lane = t & 31, w = t >> 5;
  int b  = blockIdx.x >> 2;
  int row0 = (blockIdx.x & 3) * 128;

  const uint4* s4 = reinterpret_cast<const uint4*>(d_gh2 + (size_t)b*16384);
  uint4* dst4 = reinterpret_cast<uint4*>(sm);
  #pragma unroll
  for(int q=0; q<8; q++) dst4[q*512+t] = s4[q*512+t];
  sj_sm[t] = d_sj[b*512+t] + d_eaj[t];
  if(t < 128) si_sm[t] = d_si[b*512 + row0 + t] + d_eai[row0 + t];
  __syncthreads();

  float2 bi2 = reinterpret_cast<const float2*>(gnn_bias)[lane];
  float2 ps = make_float2(0.f,0.f), pq = make_float2(0.f,0.f);

  for(int it=0; it<8; it++){
    int il = w*8 + it;            // local row 0..127
    int i  = row0 + il;           // node in batch
    unsigned packed;
    {
      int src = (lane < Kk) ? d_topk[i*Kk + lane] : i;  // lane 20 -> self
      float z;
      if(lane <= Kk){
        z = si_sm[il] + sj_sm[src];
        z = (z > 0.f) ? z : 0.2f*z;
        if(lane < Kk && src == i) z = -INFINITY;
      } else z = -INFINITY;
      float e = (lane <= Kk) ? __expf(z) : 0.f;   // no max-subtract (z bounded)
      float s = warpSum(e);
      float a = e / s;
      packed = (__float_as_uint(a) & 0xFFFFFE00u) | (unsigned)src;
    }
    float2 acc = make_float2(0.f,0.f);
    #pragma unroll
    for(int e=0; e<=Kk; e++){
      unsigned pk = __shfl_sync(0xffffffffu, packed, e);
      float a  = __uint_as_float(pk & 0xFFFFFE00u);
      int srow = (int)(pk & 511u);
      float2 v = __half22float2(gh_sm[srow*32 + lane]);
      acc.x += a*v.x; acc.y += a*v.y;
    }
    acc.x += bi2.x; acc.y += bi2.y;
    reinterpret_cast<float2*>(&d_agg[(size_t)(b*512+i)*64])[lane] = acc;
    ps.x += acc.x; ps.y += acc.y;
    pq.x += acc.x*acc.x; pq.y += acc.y*acc.y;
  }

  __syncthreads();
  float* rS = sm;          // 16*64
  float* rQ = sm + 1024;   // 16*64
  rS[w*64 + lane*2]   = ps.x;
  rS[w*64 + lane*2+1] = ps.y;
  rQ[w*64 + lane*2]   = pq.x;
  rQ[w*64 + lane*2+1] = pq.y;
  __syncthreads();
  if(t < 64){
    float S=0.f, Q=0.f;
    #pragma unroll
    for(int ww=0; ww<16; ww++){ S += rS[ww*64+t]; Q += rQ[ww*64+t]; }
    d_ps1[t*AGRID + blockIdx.x] = S;
    d_pq1[t*AGRID + blockIdx.x] = Q;
  }
}

// ---- K3: fused tail with agg smem cache (32KB dyn) ----
__device__ __forceinline__ void gridBarrier(){
  __threadfence();
  __syncthreads();
  if(threadIdx.x == 0){
    unsigned old = atomicAdd(&g_bar, 1u);
    unsigned target = (old/(unsigned)TGRID + 1u) * (unsigned)TGRID;
    while(((*(volatile unsigned*)&g_bar) - target) & 0x80000000u) __nanosleep(16);
  }
  __syncthreads();
}

__device__ __forceinline__ void reduceScale(const float* __restrict__ ps,
                                            const float* __restrict__ pq,
                                            int nblk,
                                            const float* __restrict__ gamma,
                                            const float* __restrict__ beta,
                                            float* __restrict__ scale,
                                            float* __restrict__ shift,
                                            float* shS, float* shQ){
  int c = blockIdx.x, t = threadIdx.x;
  float s = ps[c*nblk + t] + ps[c*nblk + t + 256];
  float q = pq[c*nblk + t] + pq[c*nblk + t + 256];
  s = warpSum(s); q = warpSum(q);
  if((t&31)==0){ shS[t>>5]=s; shQ[t>>5]=q; }
  __syncthreads();
  if(t==0){
    float S=0.f, Q=0.f;
    #pragma unroll
    for(int ww=0; ww<8; ww++){ S+=shS[ww]; Q+=shQ[ww]; }
    float mu  = S * (1.0f/(float)BN);
    float var = Q * (1.0f/(float)BN) - mu*mu;
    float sc  = gamma[c] * rsqrtf(var + 1e-5f);
    scale[c] = sc;
    shift[c] = beta[c] - mu*sc;
  }
}

#define TAIL_SMEM (2048*16)   // 2048 float4 agg cache = 32KB

__global__ void __launch_bounds__(256,4) k_tail(const float* __restrict__ embed,
                      const float* __restrict__ g1, const float* __restrict__ b1,
                      const float* __restrict__ g2, const float* __restrict__ b2,
                      const float* __restrict__ outW, const float* __restrict__ outB,
                      float* __restrict__ out){
  extern __shared__ float4 aggc[];          // 2048 float4 (this block's 128 rows)
  __shared__ float shp[1024], shq2[1024];
  int t = threadIdx.x;

  // phase 1: BN1 scale/shift (blocks 0..63; attn wrote d_ps1[64][AGRID=512])
  if(blockIdx.x < 64)
    reduceScale(d_ps1, d_pq1, AGRID, g1, b1, d_scale1, d_shift1, shp, shq2);
  gridBarrier();

  // phase 2: BN2 stats over h1 = relu(bn1(agg))*embed ; cache agg slice in smem
  {
    int d0 = (t & 15) * 4;
    float4 sc1 = *reinterpret_cast<const float4*>(&d_scale1[d0]);
    float4 sh1 = *reinterpret_cast<const float4*>(&d_shift1[d0]);
    float4 psum = make_float4(0.f,0.f,0.f,0.f);
    float4 psq  = make_float4(0.f,0.f,0.f,0.f);
    #pragma unroll
    for(int q=0; q<8; q++){
      int i = blockIdx.x*2048 + q*256 + t;   // (i&15)==(t&15)
      int row  = i >> 4;
      int node = row & (Nn-1);
      float4 a  = reinterpret_cast<const float4*>(d_agg)[i];
      aggc[q*256 + t] = a;
      float4 em = reinterpret_cast<const float4*>(embed)[node*16 + (t&15)];
      float4 r;
      r.x = fmaxf(a.x*sc1.x+sh1.x, 0.f)*em.x;
      r.y = fmaxf(a.y*sc1.y+sh1.y, 0.f)*em.y;
      r.z = fmaxf(a.z*sc1.z+sh1.z, 0.f)*em.z;
      r.w = fmaxf(a.w*sc1.w+sh1.w, 0.f)*em.w;
      psum.x += r.x; psum.y += r.y; psum.z += r.z; psum.w += r.w;
      psq.x += r.x*r.x; psq.y += r.y*r.y; psq.z += r.z*r.z; psq.w += r.w*r.w;
    }
    __syncthreads();
    shp[t*4+0]=psum.x; shp[t*4+1]=psum.y; shp[t*4+2]=psum.z; shp[t*4+3]=psum.w;
    shq2[t*4+0]=psq.x; shq2[t*4+1]=psq.y; shq2[t*4+2]=psq.z; shq2[t*4+3]=psq.w;
    __syncthreads();
    if(t < 64){
      int gi = t >> 2, comp = t & 3;
      float S=0.f, Q=0.f;
      #pragma unroll
      for(int m=0; m<16; m++){
        S += shp [(gi + m*16)*4 + comp];
        Q += shq2[(gi + m*16)*4 + comp];
      }
      d_ps2[t*TGRID + blockIdx.x] = S;
      d_pq2[t*TGRID + blockIdx.x] = Q;
    }
  }
  gridBarrier();

  // phase 3: BN2 scale/shift
  if(blockIdx.x < 64)
    reduceScale(d_ps2, d_pq2, TGRID, g2, b2, d_scale2, d_shift2, shp, shq2);
  gridBarrier();

  // phase 4: out from smem-cached agg
  {
    int sub = t & 15;
    float4 s1  = *reinterpret_cast<const float4*>(&d_scale1[sub*4]);
    float4 h1_ = *reinterpret_cast<const float4*>(&d_shift1[sub*4]);
    float4 s2  = *reinterpret_cast<const float4*>(&d_scale2[sub*4]);
    float4 h2_ = *reinterpret_cast<const float4*>(&d_shift2[sub*4]);
    float4 ow  = *reinterpret_cast<const float4*>(&outW[sub*4]);
    float ob = outB[0];
    #pragma unroll
    for(int it=0; it<8; it++){
      int row  = blockIdx.x*128 + it*16 + (t >> 4);
      int node = row & (Nn-1);
      float4 a  = aggc[it*256 + t];      // same layout as phase-2 store
      float4 em = *reinterpret_cast<const float4*>(&embed[node*64 + sub*4]);
      float hx = fmaxf(a.x*s1.x+h1_.x,0.f)*em.x;
      float hy = fmaxf(a.y*s1.y+h1_.y,0.f)*em.y;
      float hz = fmaxf(a.z*s1.z+h1_.z,0.f)*em.z;
      float hw = fmaxf(a.w*s1.w+h1_.w,0.f)*em.w;
      float p = fmaxf(hx*s2.x+h2_.x,0.f)*ow.x + fmaxf(hy*s2.y+h2_.y,0.f)*ow.y
              + fmaxf(hz*s2.z+h2_.z,0.f)*ow.z + fmaxf(hw*s2.w+h2_.w,0.f)*ow.w;
      #pragma unroll
      for(int o=8; o; o>>=1) p += __shfl_xor_sync(0xffffffffu, p, o);
      if(sub==0) out[row] = p + ob;
    }
  }
}

extern "C" void kernel_launch(void* const* d_in, const int* in_sizes, int n_in,
                              void* d_out, int out_size){
  int iData, iEmbed, iW, iAtI, iAtJ, iAemI, iAemJ, iBias, iG1, iB1, iG2, iB2, iOW, iOB;
  if(n_in >= 15 && in_sizes[1] == 2048){
    iData=0; iEmbed=2; iW=3; iAtI=4; iAtJ=5; iAemI=6; iAemJ=7; iBias=8;
    iG1=9; iB1=10; iG2=11; iB2=12; iOW=13; iOB=14;
  } else {
    iData=0; iEmbed=1; iW=2; iAtI=3; iAtJ=4; iAemI=5; iAemJ=6; iBias=7;
    iG1=8; iB1=9; iG2=10; iB2=11; iOW=12; iOB=13;
  }
  const float* data  = (const float*)d_in[iData];
  const float* embed = (const float*)d_in[iEmbed];
  const float* W     = (const float*)d_in[iW];
  const float* atI   = (const float*)d_in[iAtI];
  const float* atJ   = (const float*)d_in[iAtJ];
  const float* aemI  = (const float*)d_in[iAemI];
  const float* aemJ  = (const float*)d_in[iAemJ];
  const float* bias  = (const float*)d_in[iBias];
  const float* g1    = (const float*)d_in[iG1];
  const float* b1    = (const float*)d_in[iB1];
  const float* g2    = (const float*)d_in[iG2];
  const float* b2    = (const float*)d_in[iB2];
  const float* outW  = (const float*)d_in[iOW];
  const float* outB  = (const float*)d_in[iOB];
  float* out = (float*)d_out;

  cudaFuncSetAttribute(k_work, cudaFuncAttributeMaxDynamicSharedMemorySize, WORK_SMEM);
  cudaFuncSetAttribute(k_attn, cudaFuncAttributeMaxDynamicSharedMemorySize, ATTN_SMEM_BYTES);
  cudaFuncSetAttribute(k_tail, cudaFuncAttributeMaxDynamicSharedMemorySize, TAIL_SMEM);

  k_work <<<64 + BN/128, 256, WORK_SMEM>>>(data, W, atI, atJ, embed, aemI, aemJ);
  k_attn <<<AGRID, 512, ATTN_SMEM_BYTES>>>(bias);
  k_tail <<<TGRID, 256, TAIL_SMEM>>>(embed, g1, b1, g2, b2, outW, outB, out);
}